// round 1
// baseline (speedup 1.0000x reference)
#include <cuda_runtime.h>

// DynamicSparseAttention — sm_103a
// Key insight: top-k indices are always [0..15]; attention uses only the first
// K=16 tokens per batch. Re-associate the projections through the tiny
// attention: logits = x @ KQ^T, out = softmax @ VP.  W_rel is dead code.

#define Bn   4
#define Tn   1024
#define Cn   1024
#define Hn   16
#define HDn  64
#define KSn  16
#define HKn  256   // Hn*KSn

// scratch (static device globals — no allocation allowed)
__device__ float g_k [Bn*KSn*Cn];    // [b*16+slot][c]
__device__ float g_v [Bn*KSn*Cn];
__device__ float g_KQ[Bn*HKn*Cn];    // [b*256 + h*16+slot][c], scale 1/8 folded in
__device__ float g_VP[Bn*HKn*Cn];    // [b*256 + h*16+slot][j]
__device__ float g_w [Bn*Tn*HKn];    // softmax weights [b][t][h*16+slot]

// ---------------------------------------------------------------------------
// K1: k,v for the first 16 tokens of each batch.
// GEMM: M=64 rows (b,slot), N=2048 (k then v), depth 1024.
// grid 32 (N/64), block 256, 4x4 thread tile.
// ---------------------------------------------------------------------------
__global__ __launch_bounds__(256) void kv_kernel(const float* __restrict__ x,
                                                 const float* __restrict__ Wa) {
    __shared__ float As[32][68];   // [depth][m]
    __shared__ float Bs[32][68];   // [depth][n]
    const int jt  = blockIdx.x;          // 0..31
    const int tid = threadIdx.x;
    const int m0  = (tid >> 4) << 2;
    const int n0  = (tid & 15) << 2;
    const int lr  = tid >> 3;            // 0..31
    const int lf4 = (tid & 7) << 2;      // 0..28

    float acc[4][4];
#pragma unroll
    for (int i = 0; i < 4; ++i)
#pragma unroll
        for (int j = 0; j < 4; ++j) acc[i][j] = 0.f;

    for (int k0 = 0; k0 < Cn; k0 += 32) {
#pragma unroll
        for (int p = 0; p < 2; ++p) {
            const int r = lr + p * 32;               // 0..63
            const int b = r >> 4, s = r & 15;
            float4 va = *(const float4*)&x[(b*Tn + s)*Cn + k0 + lf4];
            As[lf4+0][r] = va.x; As[lf4+1][r] = va.y;
            As[lf4+2][r] = va.z; As[lf4+3][r] = va.w;
            const int jg = jt*64 + r;                // 0..2047
            float4 vb = *(const float4*)&Wa[(Cn + jg)*Cn + k0 + lf4];
            Bs[lf4+0][r] = vb.x; Bs[lf4+1][r] = vb.y;
            Bs[lf4+2][r] = vb.z; Bs[lf4+3][r] = vb.w;
        }
        __syncthreads();
#pragma unroll 8
        for (int kk = 0; kk < 32; ++kk) {
            float4 a = *(const float4*)&As[kk][m0];
            float4 b = *(const float4*)&Bs[kk][n0];
            acc[0][0] += a.x*b.x; acc[0][1] += a.x*b.y; acc[0][2] += a.x*b.z; acc[0][3] += a.x*b.w;
            acc[1][0] += a.y*b.x; acc[1][1] += a.y*b.y; acc[1][2] += a.y*b.z; acc[1][3] += a.y*b.w;
            acc[2][0] += a.z*b.x; acc[2][1] += a.z*b.y; acc[2][2] += a.z*b.z; acc[2][3] += a.z*b.w;
            acc[3][0] += a.w*b.x; acc[3][1] += a.w*b.y; acc[3][2] += a.w*b.z; acc[3][3] += a.w*b.w;
        }
        __syncthreads();
    }
#pragma unroll
    for (int i = 0; i < 4; ++i) {
        const int r = m0 + i;
#pragma unroll
        for (int j = 0; j < 4; ++j) {
            const int jg = jt*64 + n0 + j;
            if (jg < Cn) g_k[r*Cn + jg] = acc[i][j];
            else         g_v[r*Cn + (jg - Cn)] = acc[i][j];
        }
    }
}

// ---------------------------------------------------------------------------
// K2: KQ[b,h,slot,c] = 0.125 * sum_d Wq[h*64+d, c] * k[b,slot,h*64+d]
// grid (8 c-tiles of 128, 16 heads), block 256, 4x8 thread tile, depth 64.
// ---------------------------------------------------------------------------
__global__ __launch_bounds__(256) void kq_kernel(const float* __restrict__ Wa) {
    __shared__ float Wq_s[64][128];   // [d][c]  32KB
    __shared__ float ks_t[64][64];    // [d][r]  16KB
    const int ct  = blockIdx.x;       // 0..7
    const int h   = blockIdx.y;       // 0..15
    const int tid = threadIdx.x;

#pragma unroll
    for (int p = 0; p < 8; ++p) {                 // 64 d x 32 float4
        const int idx = tid + p*256;
        const int d   = idx >> 5;
        const int f4  = (idx & 31) << 2;
        float4 v = *(const float4*)&Wa[(h*HDn + d)*Cn + ct*128 + f4];
        *(float4*)&Wq_s[d][f4] = v;
    }
#pragma unroll
    for (int p = 0; p < 4; ++p) {                 // 64 r x 16 float4 over d
        const int idx = tid + p*256;
        const int r   = idx >> 4;
        const int f4  = (idx & 15) << 2;
        float4 v = *(const float4*)&g_k[r*Cn + h*HDn + f4];
        ks_t[f4+0][r] = v.x; ks_t[f4+1][r] = v.y;
        ks_t[f4+2][r] = v.z; ks_t[f4+3][r] = v.w;
    }
    __syncthreads();

    const int r0 = (tid >> 4) << 2;
    const int c0 = (tid & 15) << 3;
    float acc[4][8];
#pragma unroll
    for (int i = 0; i < 4; ++i)
#pragma unroll
        for (int j = 0; j < 8; ++j) acc[i][j] = 0.f;

#pragma unroll 8
    for (int d = 0; d < 64; ++d) {
        float4 a  = *(const float4*)&ks_t[d][r0];
        float4 b0 = *(const float4*)&Wq_s[d][c0];
        float4 b1 = *(const float4*)&Wq_s[d][c0+4];
        const float av[4] = {a.x, a.y, a.z, a.w};
        const float bv[8] = {b0.x,b0.y,b0.z,b0.w,b1.x,b1.y,b1.z,b1.w};
#pragma unroll
        for (int i = 0; i < 4; ++i)
#pragma unroll
            for (int j = 0; j < 8; ++j) acc[i][j] += av[i]*bv[j];
    }
#pragma unroll
    for (int i = 0; i < 4; ++i) {
        const int r = r0 + i, b = r >> 4, s = r & 15;
        float* dst = &g_KQ[(b*HKn + h*KSn + s)*Cn + ct*128 + c0];
#pragma unroll
        for (int j = 0; j < 8; ++j) dst[j] = acc[i][j] * 0.125f;
    }
}

// ---------------------------------------------------------------------------
// K3: VP[b,h,slot,j] = sum_d v[b,slot,h*64+d] * Wproj[j, h*64+d]
// ---------------------------------------------------------------------------
__global__ __launch_bounds__(256) void vp_kernel(const float* __restrict__ Wp) {
    __shared__ float Wp_s[64][128];   // [d][j]  (transposed on load)
    __shared__ float vs_t[64][64];    // [d][r]
    const int jt  = blockIdx.x;
    const int h   = blockIdx.y;
    const int tid = threadIdx.x;

#pragma unroll
    for (int p = 0; p < 8; ++p) {                 // 128 j x 16 float4 over d
        const int idx = tid + p*256;
        const int j   = idx >> 4;
        const int f4  = (idx & 15) << 2;
        float4 v = *(const float4*)&Wp[(jt*128 + j)*Cn + h*HDn + f4];
        Wp_s[f4+0][j] = v.x; Wp_s[f4+1][j] = v.y;
        Wp_s[f4+2][j] = v.z; Wp_s[f4+3][j] = v.w;
    }
#pragma unroll
    for (int p = 0; p < 4; ++p) {
        const int idx = tid + p*256;
        const int r   = idx >> 4;
        const int f4  = (idx & 15) << 2;
        float4 v = *(const float4*)&g_v[r*Cn + h*HDn + f4];
        vs_t[f4+0][r] = v.x; vs_t[f4+1][r] = v.y;
        vs_t[f4+2][r] = v.z; vs_t[f4+3][r] = v.w;
    }
    __syncthreads();

    const int r0 = (tid >> 4) << 2;
    const int c0 = (tid & 15) << 3;
    float acc[4][8];
#pragma unroll
    for (int i = 0; i < 4; ++i)
#pragma unroll
        for (int j = 0; j < 8; ++j) acc[i][j] = 0.f;

#pragma unroll 8
    for (int d = 0; d < 64; ++d) {
        float4 a  = *(const float4*)&vs_t[d][r0];
        float4 b0 = *(const float4*)&Wp_s[d][c0];
        float4 b1 = *(const float4*)&Wp_s[d][c0+4];
        const float av[4] = {a.x, a.y, a.z, a.w};
        const float bv[8] = {b0.x,b0.y,b0.z,b0.w,b1.x,b1.y,b1.z,b1.w};
#pragma unroll
        for (int i = 0; i < 4; ++i)
#pragma unroll
            for (int j = 0; j < 8; ++j) acc[i][j] += av[i]*bv[j];
    }
#pragma unroll
    for (int i = 0; i < 4; ++i) {
        const int r = r0 + i, b = r >> 4, s = r & 15;
        float* dst = &g_VP[(b*HKn + h*KSn + s)*Cn + jt*128 + c0];
#pragma unroll
        for (int j = 0; j < 8; ++j) dst[j] = acc[i][j];
    }
}

// ---------------------------------------------------------------------------
// K4: logits = x @ KQ^T  (per batch: 1024 x 256, depth 1024) + fused softmax.
// grid (32 t-tiles of 32, 4 batches), block 256, thread tile 4x8 over 32x256.
// ---------------------------------------------------------------------------
__global__ __launch_bounds__(256) void attn_kernel(const float* __restrict__ x) {
    __shared__ float xs [32][36];     // [depth][t]
    __shared__ float kqs[32][264];    // [depth][n]; reused as logits buffer
    const int tt  = blockIdx.x;
    const int b   = blockIdx.y;
    const int tid = threadIdx.x;
    const int t0  = tt * 32;
    const int lr  = tid >> 3;
    const int lf4 = (tid & 7) << 2;
    const int m0  = (tid >> 5) << 2;   // t rows
    const int n0  = (tid & 31) << 3;   // n cols

    float acc[4][8];
#pragma unroll
    for (int i = 0; i < 4; ++i)
#pragma unroll
        for (int j = 0; j < 8; ++j) acc[i][j] = 0.f;

    for (int k0 = 0; k0 < Cn; k0 += 32) {
        {
            float4 v = *(const float4*)&x[(b*Tn + t0 + lr)*Cn + k0 + lf4];
            xs[lf4+0][lr] = v.x; xs[lf4+1][lr] = v.y;
            xs[lf4+2][lr] = v.z; xs[lf4+3][lr] = v.w;
        }
#pragma unroll
        for (int p = 0; p < 8; ++p) {
            const int n = lr + p*32;
            float4 v = *(const float4*)&g_KQ[(b*HKn + n)*Cn + k0 + lf4];
            kqs[lf4+0][n] = v.x; kqs[lf4+1][n] = v.y;
            kqs[lf4+2][n] = v.z; kqs[lf4+3][n] = v.w;
        }
        __syncthreads();
#pragma unroll 4
        for (int kk = 0; kk < 32; ++kk) {
            float4 a  = *(const float4*)&xs[kk][m0];
            float4 b0 = *(const float4*)&kqs[kk][n0];
            float4 b1 = *(const float4*)&kqs[kk][n0+4];
            const float av[4] = {a.x, a.y, a.z, a.w};
            const float bv[8] = {b0.x,b0.y,b0.z,b0.w,b1.x,b1.y,b1.z,b1.w};
#pragma unroll
            for (int i = 0; i < 4; ++i)
#pragma unroll
                for (int j = 0; j < 8; ++j) acc[i][j] += av[i]*bv[j];
        }
        __syncthreads();
    }

    float* lg = &kqs[0][0];           // 32*256 logits, fits in kqs (32*264)
#pragma unroll
    for (int i = 0; i < 4; ++i)
#pragma unroll
        for (int j = 0; j < 8; ++j)
            lg[(m0+i)*256 + n0 + j] = acc[i][j];
    __syncthreads();

    // softmax over 16 slots per (t,h); 32 t x 16 h = 512 groups, 2 per thread
#pragma unroll
    for (int p = 0; p < 2; ++p) {
        const int g  = tid + p*256;
        const int tl = g >> 4;
        const int h  = g & 15;
        const int tg = t0 + tl;
        const int cnt = (tg + 1 < KSn) ? tg + 1 : KSn;   // valid slots: slot<=t
        const float* row = &lg[tl*256 + h*KSn];
        float m = -3.0e38f;
#pragma unroll
        for (int s = 0; s < KSn; ++s) if (s < cnt) m = fmaxf(m, row[s]);
        float e[KSn]; float sum = 0.f;
#pragma unroll
        for (int s = 0; s < KSn; ++s) {
            float v = (s < cnt) ? expf(row[s] - m) : 0.f;
            e[s] = v; sum += v;
        }
        const float inv = 1.f / sum;
        float* wout = &g_w[(b*Tn + tg)*HKn + h*KSn];
#pragma unroll
        for (int s = 0; s < KSn; ++s) wout[s] = e[s] * inv;
    }
}

// ---------------------------------------------------------------------------
// K6: out = w @ VP  (per batch: 1024 x 1024, depth 256), direct to d_out.
// grid (16 j-tiles, 16 t-tiles, 4 batches), block 256, 4x4 thread tile.
// ---------------------------------------------------------------------------
__global__ __launch_bounds__(256) void out_kernel(float* __restrict__ out) {
    __shared__ float ws [32][68];     // [depth n][t]
    __shared__ float vps[32][64];     // [depth n][j]
    const int jt  = blockIdx.x;
    const int ttb = blockIdx.y;
    const int b   = blockIdx.z;
    const int t0  = ttb * 64;
    const int j0  = jt * 64;
    const int tid = threadIdx.x;
    const int m0  = (tid >> 4) << 2;
    const int n0  = (tid & 15) << 2;
    const int lr  = tid >> 3;
    const int lf4 = (tid & 7) << 2;

    float acc[4][4];
#pragma unroll
    for (int i = 0; i < 4; ++i)
#pragma unroll
        for (int j = 0; j < 4; ++j) acc[i][j] = 0.f;

    for (int k0 = 0; k0 < HKn; k0 += 32) {
#pragma unroll
        for (int p = 0; p < 2; ++p) {
            const int r = lr + p*32;
            float4 v = *(const float4*)&g_w[(b*Tn + t0 + r)*HKn + k0 + lf4];
            ws[lf4+0][r] = v.x; ws[lf4+1][r] = v.y;
            ws[lf4+2][r] = v.z; ws[lf4+3][r] = v.w;
        }
#pragma unroll
        for (int p = 0; p < 2; ++p) {
            const int idx = tid + p*256;
            const int n   = idx >> 4;
            const int f4  = (idx & 15) << 2;
            float4 v = *(const float4*)&g_VP[(b*HKn + k0 + n)*Cn + j0 + f4];
            *(float4*)&vps[n][f4] = v;
        }
        __syncthreads();
#pragma unroll 8
        for (int kk = 0; kk < 32; ++kk) {
            float4 a = *(const float4*)&ws[kk][m0];
            float4 bb = *(const float4*)&vps[kk][n0];
            acc[0][0] += a.x*bb.x; acc[0][1] += a.x*bb.y; acc[0][2] += a.x*bb.z; acc[0][3] += a.x*bb.w;
            acc[1][0] += a.y*bb.x; acc[1][1] += a.y*bb.y; acc[1][2] += a.y*bb.z; acc[1][3] += a.y*bb.w;
            acc[2][0] += a.z*bb.x; acc[2][1] += a.z*bb.y; acc[2][2] += a.z*bb.z; acc[2][3] += a.z*bb.w;
            acc[3][0] += a.w*bb.x; acc[3][1] += a.w*bb.y; acc[3][2] += a.w*bb.z; acc[3][3] += a.w*bb.w;
        }
        __syncthreads();
    }
#pragma unroll
    for (int i = 0; i < 4; ++i) {
        float* dst = &out[(b*Tn + t0 + m0 + i)*Cn + j0 + n0];
#pragma unroll
        for (int j = 0; j < 4; ++j) dst[j] = acc[i][j];
    }
}

// ---------------------------------------------------------------------------
extern "C" void kernel_launch(void* const* d_in, const int* in_sizes, int n_in,
                              void* d_out, int out_size) {
    const float* x  = (const float*)d_in[0];   // [4,1024,1024]
    const float* Wa = (const float*)d_in[1];   // [3072,1024]
    const float* Wp = (const float*)d_in[2];   // [1024,1024]
    // d_in[3] = W_rel: provably unused (top-k indices are deterministic)
    float* out = (float*)d_out;

    kv_kernel  <<<dim3(32),        256>>>(x, Wa);
    kq_kernel  <<<dim3(8, 16),     256>>>(Wa);
    vp_kernel  <<<dim3(8, 16),     256>>>(Wp);
    attn_kernel<<<dim3(32, 4),     256>>>(x);
    out_kernel <<<dim3(16, 16, 4), 256>>>(out);
}

// round 2
// speedup vs baseline: 1.2884x; 1.2884x over previous
#include <cuda_runtime.h>

// DynamicSparseAttention — sm_103a, round 2.
// top-k indices are provably [0..15]; projections re-associated through the
// 16-slot attention. This round: FFMA2 (fma.rn.f32x2) + 8x8 thread tiles in
// the two big GEMMs (logits, out) => 2x fp32 rate, 1B/FMA shared traffic.

#define Bn   4
#define Tn   1024
#define Cn   1024
#define Hn   16
#define HDn  64
#define KSn  16
#define HKn  256

typedef unsigned long long u64;

__device__ __forceinline__ u64 bcast2(float v) {
    u64 r; asm("mov.b64 %0, {%1,%1};" : "=l"(r) : "f"(v)); return r;
}
__device__ __forceinline__ void fma2(u64& d, u64 a, u64 b) {
    asm("fma.rn.f32x2 %0, %1, %2, %0;" : "+l"(d) : "l"(a), "l"(b));
}
__device__ __forceinline__ float2 unpk(u64 v) {
    float2 f; asm("mov.b64 {%0,%1}, %2;" : "=f"(f.x), "=f"(f.y) : "l"(v)); return f;
}

// scratch (static device globals — no allocation allowed)
__device__ float g_k [Bn*KSn*Cn];
__device__ float g_v [Bn*KSn*Cn];
__device__ float g_KQ[Bn*HKn*Cn];    // [b*256 + h*16+slot][c], scale 1/8 folded
__device__ float g_VP[Bn*HKn*Cn];    // [b*256 + h*16+slot][j]
__device__ float g_w [Bn*Tn*HKn];    // softmax weights

// ---------------------------------------------------------------------------
// K1: k,v for the first 16 tokens of each batch. M=64, N=2048, K=1024.
// ---------------------------------------------------------------------------
__global__ __launch_bounds__(256) void kv_kernel(const float* __restrict__ x,
                                                 const float* __restrict__ Wa) {
    __shared__ float As[32][68];
    __shared__ float Bs[32][68];
    const int jt  = blockIdx.x;
    const int tid = threadIdx.x;
    const int m0  = (tid >> 4) << 2;
    const int n0  = (tid & 15) << 2;
    const int lr  = tid >> 3;
    const int lf4 = (tid & 7) << 2;

    float acc[4][4];
#pragma unroll
    for (int i = 0; i < 4; ++i)
#pragma unroll
        for (int j = 0; j < 4; ++j) acc[i][j] = 0.f;

    for (int k0 = 0; k0 < Cn; k0 += 32) {
#pragma unroll
        for (int p = 0; p < 2; ++p) {
            const int r = lr + p * 32;
            const int b = r >> 4, s = r & 15;
            float4 va = *(const float4*)&x[(b*Tn + s)*Cn + k0 + lf4];
            As[lf4+0][r] = va.x; As[lf4+1][r] = va.y;
            As[lf4+2][r] = va.z; As[lf4+3][r] = va.w;
            const int jg = jt*64 + r;
            float4 vb = *(const float4*)&Wa[(Cn + jg)*Cn + k0 + lf4];
            Bs[lf4+0][r] = vb.x; Bs[lf4+1][r] = vb.y;
            Bs[lf4+2][r] = vb.z; Bs[lf4+3][r] = vb.w;
        }
        __syncthreads();
#pragma unroll 8
        for (int kk = 0; kk < 32; ++kk) {
            float4 a = *(const float4*)&As[kk][m0];
            float4 b = *(const float4*)&Bs[kk][n0];
            acc[0][0] += a.x*b.x; acc[0][1] += a.x*b.y; acc[0][2] += a.x*b.z; acc[0][3] += a.x*b.w;
            acc[1][0] += a.y*b.x; acc[1][1] += a.y*b.y; acc[1][2] += a.y*b.z; acc[1][3] += a.y*b.w;
            acc[2][0] += a.z*b.x; acc[2][1] += a.z*b.y; acc[2][2] += a.z*b.z; acc[2][3] += a.z*b.w;
            acc[3][0] += a.w*b.x; acc[3][1] += a.w*b.y; acc[3][2] += a.w*b.z; acc[3][3] += a.w*b.w;
        }
        __syncthreads();
    }
#pragma unroll
    for (int i = 0; i < 4; ++i) {
        const int r = m0 + i;
#pragma unroll
        for (int j = 0; j < 4; ++j) {
            const int jg = jt*64 + n0 + j;
            if (jg < Cn) g_k[r*Cn + jg] = acc[i][j];
            else         g_v[r*Cn + (jg - Cn)] = acc[i][j];
        }
    }
}

// ---------------------------------------------------------------------------
// K2: KQ[b,h,slot,c] = 0.125 * sum_d Wq[h*64+d, c] * k[b,slot,h*64+d]
// ---------------------------------------------------------------------------
__global__ __launch_bounds__(256) void kq_kernel(const float* __restrict__ Wa) {
    __shared__ float Wq_s[64][128];
    __shared__ float ks_t[64][64];
    const int ct  = blockIdx.x;
    const int h   = blockIdx.y;
    const int tid = threadIdx.x;

#pragma unroll
    for (int p = 0; p < 8; ++p) {
        const int idx = tid + p*256;
        const int d   = idx >> 5;
        const int f4  = (idx & 31) << 2;
        float4 v = *(const float4*)&Wa[(h*HDn + d)*Cn + ct*128 + f4];
        *(float4*)&Wq_s[d][f4] = v;
    }
#pragma unroll
    for (int p = 0; p < 4; ++p) {
        const int idx = tid + p*256;
        const int r   = idx >> 4;
        const int f4  = (idx & 15) << 2;
        float4 v = *(const float4*)&g_k[r*Cn + h*HDn + f4];
        ks_t[f4+0][r] = v.x; ks_t[f4+1][r] = v.y;
        ks_t[f4+2][r] = v.z; ks_t[f4+3][r] = v.w;
    }
    __syncthreads();

    const int r0 = (tid >> 4) << 2;
    const int c0 = (tid & 15) << 3;
    float acc[4][8];
#pragma unroll
    for (int i = 0; i < 4; ++i)
#pragma unroll
        for (int j = 0; j < 8; ++j) acc[i][j] = 0.f;

#pragma unroll 8
    for (int d = 0; d < 64; ++d) {
        float4 a  = *(const float4*)&ks_t[d][r0];
        float4 b0 = *(const float4*)&Wq_s[d][c0];
        float4 b1 = *(const float4*)&Wq_s[d][c0+4];
        const float av[4] = {a.x, a.y, a.z, a.w};
        const float bv[8] = {b0.x,b0.y,b0.z,b0.w,b1.x,b1.y,b1.z,b1.w};
#pragma unroll
        for (int i = 0; i < 4; ++i)
#pragma unroll
            for (int j = 0; j < 8; ++j) acc[i][j] += av[i]*bv[j];
    }
#pragma unroll
    for (int i = 0; i < 4; ++i) {
        const int r = r0 + i, b = r >> 4, s = r & 15;
        float* dst = &g_KQ[(b*HKn + h*KSn + s)*Cn + ct*128 + c0];
#pragma unroll
        for (int j = 0; j < 8; ++j) dst[j] = acc[i][j] * 0.125f;
    }
}

// ---------------------------------------------------------------------------
// K3: VP[b,h,slot,j] = sum_d v[b,slot,h*64+d] * Wproj[j, h*64+d]
// ---------------------------------------------------------------------------
__global__ __launch_bounds__(256) void vp_kernel(const float* __restrict__ Wp) {
    __shared__ float Wp_s[64][128];
    __shared__ float vs_t[64][64];
    const int jt  = blockIdx.x;
    const int h   = blockIdx.y;
    const int tid = threadIdx.x;

#pragma unroll
    for (int p = 0; p < 8; ++p) {
        const int idx = tid + p*256;
        const int j   = idx >> 4;
        const int f4  = (idx & 15) << 2;
        float4 v = *(const float4*)&Wp[(jt*128 + j)*Cn + h*HDn + f4];
        Wp_s[f4+0][j] = v.x; Wp_s[f4+1][j] = v.y;
        Wp_s[f4+2][j] = v.z; Wp_s[f4+3][j] = v.w;
    }
#pragma unroll
    for (int p = 0; p < 4; ++p) {
        const int idx = tid + p*256;
        const int r   = idx >> 4;
        const int f4  = (idx & 15) << 2;
        float4 v = *(const float4*)&g_v[r*Cn + h*HDn + f4];
        vs_t[f4+0][r] = v.x; vs_t[f4+1][r] = v.y;
        vs_t[f4+2][r] = v.z; vs_t[f4+3][r] = v.w;
    }
    __syncthreads();

    const int r0 = (tid >> 4) << 2;
    const int c0 = (tid & 15) << 3;
    float acc[4][8];
#pragma unroll
    for (int i = 0; i < 4; ++i)
#pragma unroll
        for (int j = 0; j < 8; ++j) acc[i][j] = 0.f;

#pragma unroll 8
    for (int d = 0; d < 64; ++d) {
        float4 a  = *(const float4*)&vs_t[d][r0];
        float4 b0 = *(const float4*)&Wp_s[d][c0];
        float4 b1 = *(const float4*)&Wp_s[d][c0+4];
        const float av[4] = {a.x, a.y, a.z, a.w};
        const float bv[8] = {b0.x,b0.y,b0.z,b0.w,b1.x,b1.y,b1.z,b1.w};
#pragma unroll
        for (int i = 0; i < 4; ++i)
#pragma unroll
            for (int j = 0; j < 8; ++j) acc[i][j] += av[i]*bv[j];
    }
#pragma unroll
    for (int i = 0; i < 4; ++i) {
        const int r = r0 + i, b = r >> 4, s = r & 15;
        float* dst = &g_VP[(b*HKn + h*KSn + s)*Cn + jt*128 + c0];
#pragma unroll
        for (int j = 0; j < 8; ++j) dst[j] = acc[i][j];
    }
}

// ---------------------------------------------------------------------------
// K4: logits = x @ KQ^T + fused softmax.  Tile 32(t) x 256(hk), depth 1024.
// 128 blocks x 128 threads, 8x8 per thread via FFMA2.
// ---------------------------------------------------------------------------
#define AT_KC 16
#define AT_PX 36     // 36*4 = 144 bytes, 16B-aligned rows
#define AT_PK 264    // 264*4 = 1056 bytes, 16B-aligned rows

__global__ __launch_bounds__(128) void attn2_kernel(const float* __restrict__ x) {
    __shared__ float smem[32*256];          // 32KB; GEMM buffers then logits
    float* xs  = smem;                      // [AT_KC][AT_PX]
    float* kqs = smem + AT_KC*AT_PX;        // [AT_KC][AT_PK]
    const int tid   = threadIdx.x;
    const int row0  = blockIdx.x * 32;      // global t row (0..4095)
    const int b     = row0 >> 10;
    const int lane4 = (tid & 31) * 4;       // n columns: lane4.., 128+lane4..
    const int m0    = (tid >> 5) * 8;       // 8 t-rows per thread

    u64 acc[8][4];
#pragma unroll
    for (int i = 0; i < 8; ++i)
#pragma unroll
        for (int j = 0; j < 4; ++j) acc[i][j] = 0ull;

    const int xr = tid >> 2;                // 0..31
    const int xc = (tid & 3) * 4;

    for (int k0 = 0; k0 < Cn; k0 += AT_KC) {
        {
            float4 v = *(const float4*)&x[(row0 + xr)*Cn + k0 + xc];
            xs[(xc+0)*AT_PX + xr] = v.x;
            xs[(xc+1)*AT_PX + xr] = v.y;
            xs[(xc+2)*AT_PX + xr] = v.z;
            xs[(xc+3)*AT_PX + xr] = v.w;
        }
#pragma unroll
        for (int p = 0; p < 8; ++p) {
            const int idx = tid + p*128;
            const int n   = idx >> 2;
            const int c   = (idx & 3) * 4;
            float4 v = *(const float4*)&g_KQ[(b*HKn + n)*Cn + k0 + c];
            kqs[(c+0)*AT_PK + n] = v.x;
            kqs[(c+1)*AT_PK + n] = v.y;
            kqs[(c+2)*AT_PK + n] = v.z;
            kqs[(c+3)*AT_PK + n] = v.w;
        }
        __syncthreads();
#pragma unroll
        for (int kk = 0; kk < AT_KC; ++kk) {
            float4 a0 = *(const float4*)&xs[kk*AT_PX + m0];
            float4 a1 = *(const float4*)&xs[kk*AT_PX + m0 + 4];
            ulonglong2 b0 = *(const ulonglong2*)&kqs[kk*AT_PK + lane4];
            ulonglong2 b1 = *(const ulonglong2*)&kqs[kk*AT_PK + 128 + lane4];
            const float av[8] = {a0.x,a0.y,a0.z,a0.w,a1.x,a1.y,a1.z,a1.w};
#pragma unroll
            for (int i = 0; i < 8; ++i) {
                u64 ap = bcast2(av[i]);
                fma2(acc[i][0], ap, b0.x);
                fma2(acc[i][1], ap, b0.y);
                fma2(acc[i][2], ap, b1.x);
                fma2(acc[i][3], ap, b1.y);
            }
        }
        __syncthreads();
    }

    // stage logits in smem (reuses GEMM buffers; all reads done at last bar)
    float* lg = smem;
#pragma unroll
    for (int i = 0; i < 8; ++i) {
        float2 c0 = unpk(acc[i][0]);
        float2 c1 = unpk(acc[i][1]);
        float2 c2 = unpk(acc[i][2]);
        float2 c3 = unpk(acc[i][3]);
        float* r = &lg[(m0+i)*256];
        r[lane4+0]     = c0.x; r[lane4+1]     = c0.y;
        r[lane4+2]     = c1.x; r[lane4+3]     = c1.y;
        r[128+lane4+0] = c2.x; r[128+lane4+1] = c2.y;
        r[128+lane4+2] = c3.x; r[128+lane4+3] = c3.y;
    }
    __syncthreads();

    // softmax: 32 t x 16 h = 512 groups, 4 per thread
#pragma unroll
    for (int p = 0; p < 4; ++p) {
        const int g  = tid + p*128;
        const int tl = g >> 4;
        const int h  = g & 15;
        const int tg = row0 + tl;
        const int tb = tg & (Tn - 1);
        const int cnt = (tb + 1 < KSn) ? tb + 1 : KSn;
        const float* rowp = &lg[tl*256 + h*KSn];
        float m = -3.0e38f;
#pragma unroll
        for (int s = 0; s < KSn; ++s) if (s < cnt) m = fmaxf(m, rowp[s]);
        float e[KSn]; float sum = 0.f;
#pragma unroll
        for (int s = 0; s < KSn; ++s) {
            float v = (s < cnt) ? expf(rowp[s] - m) : 0.f;
            e[s] = v; sum += v;
        }
        const float inv = 1.f / sum;
        float* wout = &g_w[tg*HKn + h*KSn];
#pragma unroll
        for (int s = 0; s < KSn; ++s) wout[s] = e[s] * inv;
    }
}

// ---------------------------------------------------------------------------
// K5: out = w @ VP.  Tile 128(t) x 128(j), depth 256.
// 256 blocks x 256 threads, 8x8 per thread via FFMA2, 2 CTAs/SM.
// ---------------------------------------------------------------------------
#define OT_KC 16
#define OT_P  136    // 136*4 = 544 bytes, 16B-aligned rows

__global__ __launch_bounds__(256,2) void out2_kernel(float* __restrict__ out) {
    __shared__ float ws [OT_KC*OT_P];   // [k][m]
    __shared__ float vps[OT_KC*OT_P];   // [k][j]
    const int jt   = blockIdx.x;        // 0..7
    const int mt   = blockIdx.y;        // 0..31
    const int tid  = threadIdx.x;
    const int row0 = mt * 128;
    const int b    = row0 >> 10;
    const int j0   = jt * 128;
    const int m0   = (tid >> 4) * 8;
    const int lane4 = (tid & 15) * 4;   // j columns: lane4.., 64+lane4..

    u64 acc[8][4];
#pragma unroll
    for (int i = 0; i < 8; ++i)
#pragma unroll
        for (int j = 0; j < 4; ++j) acc[i][j] = 0ull;

    for (int k0 = 0; k0 < HKn; k0 += OT_KC) {
#pragma unroll
        for (int p = 0; p < 2; ++p) {               // ws: transpose load
            const int idx = tid + p*256;
            const int r   = idx >> 2;               // 0..127
            const int c   = (idx & 3) * 4;
            float4 v = *(const float4*)&g_w[(row0 + r)*HKn + k0 + c];
            ws[(c+0)*OT_P + r] = v.x;
            ws[(c+1)*OT_P + r] = v.y;
            ws[(c+2)*OT_P + r] = v.z;
            ws[(c+3)*OT_P + r] = v.w;
        }
#pragma unroll
        for (int p = 0; p < 2; ++p) {               // vps: direct copy
            const int idx = tid + p*256;
            const int kk  = idx >> 5;               // 0..15
            const int jf  = (idx & 31) * 4;
            float4 v = *(const float4*)&g_VP[(b*HKn + k0 + kk)*Cn + j0 + jf];
            *(float4*)&vps[kk*OT_P + jf] = v;
        }
        __syncthreads();
#pragma unroll
        for (int kk = 0; kk < OT_KC; ++kk) {
            float4 a0 = *(const float4*)&ws[kk*OT_P + m0];
            float4 a1 = *(const float4*)&ws[kk*OT_P + m0 + 4];
            ulonglong2 b0 = *(const ulonglong2*)&vps[kk*OT_P + lane4];
            ulonglong2 b1 = *(const ulonglong2*)&vps[kk*OT_P + 64 + lane4];
            const float av[8] = {a0.x,a0.y,a0.z,a0.w,a1.x,a1.y,a1.z,a1.w};
#pragma unroll
            for (int i = 0; i < 8; ++i) {
                u64 ap = bcast2(av[i]);
                fma2(acc[i][0], ap, b0.x);
                fma2(acc[i][1], ap, b0.y);
                fma2(acc[i][2], ap, b1.x);
                fma2(acc[i][3], ap, b1.y);
            }
        }
        __syncthreads();
    }
#pragma unroll
    for (int i = 0; i < 8; ++i) {
        float2 c0 = unpk(acc[i][0]);
        float2 c1 = unpk(acc[i][1]);
        float2 c2 = unpk(acc[i][2]);
        float2 c3 = unpk(acc[i][3]);
        float* dst = &out[(row0 + m0 + i)*Cn + j0];
        *(float4*)&dst[lane4]      = make_float4(c0.x, c0.y, c1.x, c1.y);
        *(float4*)&dst[64 + lane4] = make_float4(c2.x, c2.y, c3.x, c3.y);
    }
}

// ---------------------------------------------------------------------------
extern "C" void kernel_launch(void* const* d_in, const int* in_sizes, int n_in,
                              void* d_out, int out_size) {
    const float* x  = (const float*)d_in[0];
    const float* Wa = (const float*)d_in[1];
    const float* Wp = (const float*)d_in[2];
    float* out = (float*)d_out;

    kv_kernel   <<<dim3(32),     256>>>(x, Wa);
    kq_kernel   <<<dim3(8, 16),  256>>>(Wa);
    vp_kernel   <<<dim3(8, 16),  256>>>(Wp);
    attn2_kernel<<<dim3(128),    128>>>(x);
    out2_kernel <<<dim3(8, 32),  256>>>(out);
}

// round 3
// speedup vs baseline: 1.6763x; 1.3010x over previous
#include <cuda_runtime.h>

// DynamicSparseAttention — sm_103a, round 3.
// top-k indices are provably [0..15]. Round 3: occupancy. Split-K attn
// (512 CTAs, 12 warps/SM), split-K kv, merged kq+vp, 64x128 out tiles.
// All big GEMMs: 8x8 per-thread tiles via fma.rn.f32x2 (1.0 B/FMA smem).

#define Bn   4
#define Tn   1024
#define Cn   1024
#define Hn   16
#define HDn  64
#define KSn  16
#define HKn  256

typedef unsigned long long u64;

__device__ __forceinline__ u64 bcast2(float v) {
    u64 r; asm("mov.b64 %0, {%1,%1};" : "=l"(r) : "f"(v)); return r;
}
__device__ __forceinline__ void fma2(u64& d, u64 a, u64 b) {
    asm("fma.rn.f32x2 %0, %1, %2, %0;" : "+l"(d) : "l"(a), "l"(b));
}
__device__ __forceinline__ float2 unpk(u64 v) {
    float2 f; asm("mov.b64 {%0,%1}, %2;" : "=f"(f.x), "=f"(f.y) : "l"(v)); return f;
}

// scratch (static device globals — no allocation allowed)
__device__ float g_k  [Bn*KSn*Cn];
__device__ float g_v  [Bn*KSn*Cn];
__device__ float g_kvp[4*64*2048];       // kv split-K partials
__device__ float g_KQ [Bn*HKn*Cn];       // scale 1/8 folded
__device__ float g_VP [Bn*HKn*Cn];
__device__ float g_lp [4*Bn*Tn*HKn];     // attn split-K partial logits (16MB)
__device__ float g_w  [Bn*Tn*HKn];       // softmax weights

// ---------------------------------------------------------------------------
// K1: kv partials. grid (32 n-tiles of 64, 4 k-splits), 256 thr, 4x4 tiles.
// ---------------------------------------------------------------------------
__global__ __launch_bounds__(256) void kv3_kernel(const float* __restrict__ x,
                                                  const float* __restrict__ Wa) {
    __shared__ float As[32][68];
    __shared__ float Bs[32][68];
    const int jt  = blockIdx.x;          // 0..31
    const int ks  = blockIdx.y;          // 0..3
    const int tid = threadIdx.x;
    const int m0  = (tid >> 4) << 2;
    const int n0  = (tid & 15) << 2;
    const int lr  = tid >> 3;
    const int lf4 = (tid & 7) << 2;
    const int kbase = ks * 256;

    float acc[4][4];
#pragma unroll
    for (int i = 0; i < 4; ++i)
#pragma unroll
        for (int j = 0; j < 4; ++j) acc[i][j] = 0.f;

    for (int k0 = kbase; k0 < kbase + 256; k0 += 32) {
#pragma unroll
        for (int p = 0; p < 2; ++p) {
            const int r = lr + p * 32;
            const int b = r >> 4, s = r & 15;
            float4 va = *(const float4*)&x[(b*Tn + s)*Cn + k0 + lf4];
            As[lf4+0][r] = va.x; As[lf4+1][r] = va.y;
            As[lf4+2][r] = va.z; As[lf4+3][r] = va.w;
            const int jg = jt*64 + r;
            float4 vb = *(const float4*)&Wa[(Cn + jg)*Cn + k0 + lf4];
            Bs[lf4+0][r] = vb.x; Bs[lf4+1][r] = vb.y;
            Bs[lf4+2][r] = vb.z; Bs[lf4+3][r] = vb.w;
        }
        __syncthreads();
#pragma unroll 8
        for (int kk = 0; kk < 32; ++kk) {
            float4 a = *(const float4*)&As[kk][m0];
            float4 b = *(const float4*)&Bs[kk][n0];
            acc[0][0] += a.x*b.x; acc[0][1] += a.x*b.y; acc[0][2] += a.x*b.z; acc[0][3] += a.x*b.w;
            acc[1][0] += a.y*b.x; acc[1][1] += a.y*b.y; acc[1][2] += a.y*b.z; acc[1][3] += a.y*b.w;
            acc[2][0] += a.z*b.x; acc[2][1] += a.z*b.y; acc[2][2] += a.z*b.z; acc[2][3] += a.z*b.w;
            acc[3][0] += a.w*b.x; acc[3][1] += a.w*b.y; acc[3][2] += a.w*b.z; acc[3][3] += a.w*b.w;
        }
        __syncthreads();
    }
#pragma unroll
    for (int i = 0; i < 4; ++i) {
        const int r = m0 + i;
#pragma unroll
        for (int j = 0; j < 4; ++j) {
            const int jg = jt*64 + n0 + j;
            g_kvp[(ks*64 + r)*2048 + jg] = acc[i][j];
        }
    }
}

// reduce 4 kv partials into g_k / g_v.  grid 128, block 256, float4 each.
__global__ __launch_bounds__(256) void kvred_kernel() {
    const int i  = blockIdx.x*256 + threadIdx.x;   // 0..32767
    const int r  = i >> 9;
    const int jg = (i & 511) << 2;
    float4 s = make_float4(0.f, 0.f, 0.f, 0.f);
#pragma unroll
    for (int ks = 0; ks < 4; ++ks) {
        float4 v = *(const float4*)&g_kvp[(ks*64 + r)*2048 + jg];
        s.x += v.x; s.y += v.y; s.z += v.z; s.w += v.w;
    }
    if (jg < Cn) *(float4*)&g_k[r*Cn + jg] = s;
    else         *(float4*)&g_v[r*Cn + (jg - Cn)] = s;
}

// ---------------------------------------------------------------------------
// K2: merged KQ / VP.  grid (8 c-tiles, 16 heads, 2 which), 256 thr.
//   z=0: KQ[b,h,s,c] = 0.125 * sum_d Wq[h*64+d, c] * k[b,s,h*64+d]
//   z=1: VP[b,h,s,j] =          sum_d v[b,s,h*64+d] * Wproj[j, h*64+d]
// ---------------------------------------------------------------------------
__global__ __launch_bounds__(256) void kqvp_kernel(const float* __restrict__ Wa,
                                                   const float* __restrict__ Wp) {
    __shared__ float Ws[64][128];
    __shared__ float ts[64][64];
    const int ct  = blockIdx.x;
    const int h   = blockIdx.y;
    const int z   = blockIdx.z;
    const int tid = threadIdx.x;

    if (z == 0) {
#pragma unroll
        for (int p = 0; p < 8; ++p) {             // Wq rows d, cols c direct
            const int idx = tid + p*256;
            const int d   = idx >> 5;
            const int f4  = (idx & 31) << 2;
            float4 v = *(const float4*)&Wa[(h*HDn + d)*Cn + ct*128 + f4];
            *(float4*)&Ws[d][f4] = v;
        }
#pragma unroll
        for (int p = 0; p < 4; ++p) {
            const int idx = tid + p*256;
            const int r   = idx >> 4;
            const int f4  = (idx & 15) << 2;
            float4 v = *(const float4*)&g_k[r*Cn + h*HDn + f4];
            ts[f4+0][r] = v.x; ts[f4+1][r] = v.y;
            ts[f4+2][r] = v.z; ts[f4+3][r] = v.w;
        }
    } else {
#pragma unroll
        for (int p = 0; p < 8; ++p) {             // Wproj transposed
            const int idx = tid + p*256;
            const int j   = idx >> 4;
            const int f4  = (idx & 15) << 2;
            float4 v = *(const float4*)&Wp[(ct*128 + j)*Cn + h*HDn + f4];
            Ws[f4+0][j] = v.x; Ws[f4+1][j] = v.y;
            Ws[f4+2][j] = v.z; Ws[f4+3][j] = v.w;
        }
#pragma unroll
        for (int p = 0; p < 4; ++p) {
            const int idx = tid + p*256;
            const int r   = idx >> 4;
            const int f4  = (idx & 15) << 2;
            float4 v = *(const float4*)&g_v[r*Cn + h*HDn + f4];
            ts[f4+0][r] = v.x; ts[f4+1][r] = v.y;
            ts[f4+2][r] = v.z; ts[f4+3][r] = v.w;
        }
    }
    __syncthreads();

    const int r0 = (tid >> 4) << 2;
    const int c0 = (tid & 15) << 3;
    float acc[4][8];
#pragma unroll
    for (int i = 0; i < 4; ++i)
#pragma unroll
        for (int j = 0; j < 8; ++j) acc[i][j] = 0.f;

#pragma unroll 8
    for (int d = 0; d < 64; ++d) {
        float4 a  = *(const float4*)&ts[d][r0];
        float4 b0 = *(const float4*)&Ws[d][c0];
        float4 b1 = *(const float4*)&Ws[d][c0+4];
        const float av[4] = {a.x, a.y, a.z, a.w};
        const float bv[8] = {b0.x,b0.y,b0.z,b0.w,b1.x,b1.y,b1.z,b1.w};
#pragma unroll
        for (int i = 0; i < 4; ++i)
#pragma unroll
            for (int j = 0; j < 8; ++j) acc[i][j] += av[i]*bv[j];
    }

    const float scale = (z == 0) ? 0.125f : 1.0f;
    float* gout = (z == 0) ? g_KQ : g_VP;
#pragma unroll
    for (int i = 0; i < 4; ++i) {
        const int r = r0 + i, b = r >> 4, s = r & 15;
        float* dst = &gout[(b*HKn + h*KSn + s)*Cn + ct*128 + c0];
#pragma unroll
        for (int j = 0; j < 8; ++j) dst[j] = acc[i][j] * scale;
    }
}

// ---------------------------------------------------------------------------
// K3: attn partial logits = x @ KQ^T, split-K.  grid (128 t-tiles, 4 ksplits),
// 128 thr, tile 32x256, 8x8 per thread via FFMA2.
// ---------------------------------------------------------------------------
#define AT_KC 16
#define AT_PX 36
#define AT_PK 264

__global__ __launch_bounds__(128) void attn3_kernel(const float* __restrict__ x) {
    __shared__ float smem[AT_KC*(AT_PX + AT_PK)];
    float* xs  = smem;
    float* kqs = smem + AT_KC*AT_PX;
    const int tid   = threadIdx.x;
    const int row0  = blockIdx.x * 32;
    const int ks    = blockIdx.y;
    const int b     = row0 >> 10;
    const int lane4 = (tid & 31) * 4;
    const int m0    = (tid >> 5) * 8;
    const int kbase = ks * 256;

    u64 acc[8][4];
#pragma unroll
    for (int i = 0; i < 8; ++i)
#pragma unroll
        for (int j = 0; j < 4; ++j) acc[i][j] = 0ull;

    const int xr = tid >> 2;
    const int xc = (tid & 3) * 4;

    for (int k0 = kbase; k0 < kbase + 256; k0 += AT_KC) {
        {
            float4 v = *(const float4*)&x[(row0 + xr)*Cn + k0 + xc];
            xs[(xc+0)*AT_PX + xr] = v.x;
            xs[(xc+1)*AT_PX + xr] = v.y;
            xs[(xc+2)*AT_PX + xr] = v.z;
            xs[(xc+3)*AT_PX + xr] = v.w;
        }
#pragma unroll
        for (int p = 0; p < 8; ++p) {
            const int idx = tid + p*128;
            const int n   = idx >> 2;
            const int c   = (idx & 3) * 4;
            float4 v = *(const float4*)&g_KQ[(b*HKn + n)*Cn + k0 + c];
            kqs[(c+0)*AT_PK + n] = v.x;
            kqs[(c+1)*AT_PK + n] = v.y;
            kqs[(c+2)*AT_PK + n] = v.z;
            kqs[(c+3)*AT_PK + n] = v.w;
        }
        __syncthreads();
#pragma unroll
        for (int kk = 0; kk < AT_KC; ++kk) {
            float4 a0 = *(const float4*)&xs[kk*AT_PX + m0];
            float4 a1 = *(const float4*)&xs[kk*AT_PX + m0 + 4];
            ulonglong2 b0 = *(const ulonglong2*)&kqs[kk*AT_PK + lane4];
            ulonglong2 b1 = *(const ulonglong2*)&kqs[kk*AT_PK + 128 + lane4];
            const float av[8] = {a0.x,a0.y,a0.z,a0.w,a1.x,a1.y,a1.z,a1.w};
#pragma unroll
            for (int i = 0; i < 8; ++i) {
                u64 ap = bcast2(av[i]);
                fma2(acc[i][0], ap, b0.x);
                fma2(acc[i][1], ap, b0.y);
                fma2(acc[i][2], ap, b1.x);
                fma2(acc[i][3], ap, b1.y);
            }
        }
        __syncthreads();
    }

#pragma unroll
    for (int i = 0; i < 8; ++i) {
        float2 c0 = unpk(acc[i][0]);
        float2 c1 = unpk(acc[i][1]);
        float2 c2 = unpk(acc[i][2]);
        float2 c3 = unpk(acc[i][3]);
        float* dst = &g_lp[(ks*(Bn*Tn) + row0 + m0 + i)*HKn];
        *(float4*)&dst[lane4]       = make_float4(c0.x, c0.y, c1.x, c1.y);
        *(float4*)&dst[128 + lane4] = make_float4(c2.x, c2.y, c3.x, c3.y);
    }
}

// ---------------------------------------------------------------------------
// K4: sum split-K partials + masked softmax.  grid 512, 128 thr (8t x 16h).
// ---------------------------------------------------------------------------
__global__ __launch_bounds__(128) void softmax_kernel() {
    const int tid = threadIdx.x;
    const int t   = blockIdx.x * 8 + (tid >> 4);   // global row 0..4095
    const int h   = tid & 15;
    const int base = t*HKn + h*KSn;

    float4 s0 = make_float4(0,0,0,0), s1 = s0, s2 = s0, s3 = s0;
#pragma unroll
    for (int ks = 0; ks < 4; ++ks) {
        const float* p = &g_lp[ks*(Bn*Tn*HKn) + base];
        float4 v0 = *(const float4*)&p[0];
        float4 v1 = *(const float4*)&p[4];
        float4 v2 = *(const float4*)&p[8];
        float4 v3 = *(const float4*)&p[12];
        s0.x+=v0.x; s0.y+=v0.y; s0.z+=v0.z; s0.w+=v0.w;
        s1.x+=v1.x; s1.y+=v1.y; s1.z+=v1.z; s1.w+=v1.w;
        s2.x+=v2.x; s2.y+=v2.y; s2.z+=v2.z; s2.w+=v2.w;
        s3.x+=v3.x; s3.y+=v3.y; s3.z+=v3.z; s3.w+=v3.w;
    }
    float l[KSn] = {s0.x,s0.y,s0.z,s0.w, s1.x,s1.y,s1.z,s1.w,
                    s2.x,s2.y,s2.z,s2.w, s3.x,s3.y,s3.z,s3.w};
    const int tb  = t & (Tn - 1);
    const int cnt = (tb + 1 < KSn) ? tb + 1 : KSn;
    float m = -3.0e38f;
#pragma unroll
    for (int s = 0; s < KSn; ++s) if (s < cnt) m = fmaxf(m, l[s]);
    float e[KSn]; float sum = 0.f;
#pragma unroll
    for (int s = 0; s < KSn; ++s) {
        float v = (s < cnt) ? expf(l[s] - m) : 0.f;
        e[s] = v; sum += v;
    }
    const float inv = 1.f / sum;
    float* w = &g_w[base];
    *(float4*)&w[0]  = make_float4(e[0]*inv, e[1]*inv, e[2]*inv, e[3]*inv);
    *(float4*)&w[4]  = make_float4(e[4]*inv, e[5]*inv, e[6]*inv, e[7]*inv);
    *(float4*)&w[8]  = make_float4(e[8]*inv, e[9]*inv, e[10]*inv, e[11]*inv);
    *(float4*)&w[12] = make_float4(e[12]*inv, e[13]*inv, e[14]*inv, e[15]*inv);
}

// ---------------------------------------------------------------------------
// K5: out = w @ VP.  Tile 64(t) x 128(j), depth 256.
// grid (8 j-tiles, 64 m-tiles) = 512 CTAs, 128 thr, 8x8 per thread FFMA2.
// ---------------------------------------------------------------------------
#define OT_KC 16
#define OT_PW 72     // ws row pad (floats): 288B, 16B-aligned
#define OT_PV 136    // vps row pad: 544B, 16B-aligned

__global__ __launch_bounds__(128) void out3_kernel(float* __restrict__ out) {
    __shared__ float ws [OT_KC*OT_PW];   // [k][m 64]
    __shared__ float vps[OT_KC*OT_PV];   // [k][j 128]
    const int jt   = blockIdx.x;         // 0..7
    const int mt   = blockIdx.y;         // 0..63
    const int tid  = threadIdx.x;
    const int row0 = mt * 64;
    const int b    = row0 >> 10;
    const int j0   = jt * 128;
    const int m0   = (tid >> 4) * 8;     // 0..56
    const int lane4 = (tid & 15) * 4;

    u64 acc[8][4];
#pragma unroll
    for (int i = 0; i < 8; ++i)
#pragma unroll
        for (int j = 0; j < 4; ++j) acc[i][j] = 0ull;

    for (int k0 = 0; k0 < HKn; k0 += OT_KC) {
#pragma unroll
        for (int p = 0; p < 2; ++p) {               // ws: transpose load
            const int idx = tid + p*128;
            const int r   = idx >> 2;               // 0..63
            const int c   = (idx & 3) * 4;
            float4 v = *(const float4*)&g_w[(row0 + r)*HKn + k0 + c];
            ws[(c+0)*OT_PW + r] = v.x;
            ws[(c+1)*OT_PW + r] = v.y;
            ws[(c+2)*OT_PW + r] = v.z;
            ws[(c+3)*OT_PW + r] = v.w;
        }
#pragma unroll
        for (int p = 0; p < 4; ++p) {               // vps: direct copy
            const int idx = tid + p*128;
            const int kk  = idx >> 5;               // 0..15
            const int jf  = (idx & 31) * 4;
            float4 v = *(const float4*)&g_VP[(b*HKn + k0 + kk)*Cn + j0 + jf];
            *(float4*)&vps[kk*OT_PV + jf] = v;
        }
        __syncthreads();
#pragma unroll
        for (int kk = 0; kk < OT_KC; ++kk) {
            float4 a0 = *(const float4*)&ws[kk*OT_PW + m0];
            float4 a1 = *(const float4*)&ws[kk*OT_PW + m0 + 4];
            ulonglong2 b0 = *(const ulonglong2*)&vps[kk*OT_PV + lane4];
            ulonglong2 b1 = *(const ulonglong2*)&vps[kk*OT_PV + 64 + lane4];
            const float av[8] = {a0.x,a0.y,a0.z,a0.w,a1.x,a1.y,a1.z,a1.w};
#pragma unroll
            for (int i = 0; i < 8; ++i) {
                u64 ap = bcast2(av[i]);
                fma2(acc[i][0], ap, b0.x);
                fma2(acc[i][1], ap, b0.y);
                fma2(acc[i][2], ap, b1.x);
                fma2(acc[i][3], ap, b1.y);
            }
        }
        __syncthreads();
    }
#pragma unroll
    for (int i = 0; i < 8; ++i) {
        float2 c0 = unpk(acc[i][0]);
        float2 c1 = unpk(acc[i][1]);
        float2 c2 = unpk(acc[i][2]);
        float2 c3 = unpk(acc[i][3]);
        float* dst = &out[(row0 + m0 + i)*Cn + j0];
        *(float4*)&dst[lane4]      = make_float4(c0.x, c0.y, c1.x, c1.y);
        *(float4*)&dst[64 + lane4] = make_float4(c2.x, c2.y, c3.x, c3.y);
    }
}

// ---------------------------------------------------------------------------
extern "C" void kernel_launch(void* const* d_in, const int* in_sizes, int n_in,
                              void* d_out, int out_size) {
    const float* x  = (const float*)d_in[0];
    const float* Wa = (const float*)d_in[1];
    const float* Wp = (const float*)d_in[2];
    float* out = (float*)d_out;

    kv3_kernel    <<<dim3(32, 4),    256>>>(x, Wa);
    kvred_kernel  <<<dim3(128),      256>>>();
    kqvp_kernel   <<<dim3(8, 16, 2), 256>>>(Wa, Wp);
    attn3_kernel  <<<dim3(128, 4),   128>>>(x);
    softmax_kernel<<<dim3(512),      128>>>();
    out3_kernel   <<<dim3(8, 64),    128>>>(out);
}

// round 4
// speedup vs baseline: 2.7652x; 1.6496x over previous
#include <cuda_runtime.h>
#include <cuda_bf16.h>
#include <cstdint>

// DynamicSparseAttention — sm_103a, round 4: tensor cores.
// top-k indices are provably [0..15]; projections re-associated through the
// 16-slot attention. Big GEMMs (logits = x@KQ^T, out = w@VP) now run on
// HMMA m16n8k16 bf16 with 3-term hi/lo split (~fp32 accuracy).

#define Bn   4
#define Tn   1024
#define Cn   1024
#define Hn   16
#define HDn  64
#define KSn  16
#define HKn  256
#define LDT  40          // smem row stride in bf16 (80B) -> conflict-free ldmatrix

typedef unsigned long long u64;
typedef __nv_bfloat16 bf16;

// ---- scratch (static device globals; no allocation allowed) ----
__device__ float g_kvp [4*64*2048];        // kv split-K partials
__device__ bf16  g_KQh [Bn*HKn*Cn];        // KQ hi plane (scale 1/8 folded)
__device__ bf16  g_KQl [Bn*HKn*Cn];
__device__ bf16  g_VPTh[Bn*Cn*HKn];        // VP^T [b][j][hk] hi
__device__ bf16  g_VPTl[Bn*Cn*HKn];
__device__ float g_lp  [2*Bn*Tn*HKn];      // attn split-K partial logits
__device__ bf16  g_wh  [Bn*Tn*HKn];        // softmax weights hi
__device__ bf16  g_wl  [Bn*Tn*HKn];

// ---- helpers ----
__device__ __forceinline__ uint32_t sptr(const void* p) {
    return (uint32_t)__cvta_generic_to_shared(p);
}
__device__ __forceinline__ void ldsm4(uint32_t* r, uint32_t addr) {
    asm volatile("ldmatrix.sync.aligned.m8n8.x4.shared.b16 {%0,%1,%2,%3}, [%4];"
        : "=r"(r[0]), "=r"(r[1]), "=r"(r[2]), "=r"(r[3]) : "r"(addr));
}
__device__ __forceinline__ void mma16816(float* d, const uint32_t* a, const uint32_t* b) {
    asm volatile("mma.sync.aligned.m16n8k16.row.col.f32.bf16.bf16.f32 "
        "{%0,%1,%2,%3}, {%4,%5,%6,%7}, {%8,%9}, {%0,%1,%2,%3};"
        : "+f"(d[0]), "+f"(d[1]), "+f"(d[2]), "+f"(d[3])
        : "r"(a[0]), "r"(a[1]), "r"(a[2]), "r"(a[3]), "r"(b[0]), "r"(b[1]));
}
__device__ __forceinline__ uint32_t pk2(bf16 a, bf16 b) {
    __nv_bfloat162 t; t.x = a; t.y = b;
    return *reinterpret_cast<uint32_t*>(&t);
}
__device__ __forceinline__ void split2(float v, bf16& h, bf16& l) {
    h = __float2bfloat16_rn(v);
    l = __float2bfloat16_rn(v - __bfloat162float(h));
}

// ---------------------------------------------------------------------------
// K1: kv partials. grid (32 n-tiles of 64, 4 k-splits), 256 thr, 4x4 tiles.
// ---------------------------------------------------------------------------
__global__ __launch_bounds__(256) void kv3_kernel(const float* __restrict__ x,
                                                  const float* __restrict__ Wa) {
    __shared__ float As[32][68];
    __shared__ float Bs[32][68];
    const int jt  = blockIdx.x;
    const int ks  = blockIdx.y;
    const int tid = threadIdx.x;
    const int m0  = (tid >> 4) << 2;
    const int n0  = (tid & 15) << 2;
    const int lr  = tid >> 3;
    const int lf4 = (tid & 7) << 2;
    const int kbase = ks * 256;

    float acc[4][4];
#pragma unroll
    for (int i = 0; i < 4; ++i)
#pragma unroll
        for (int j = 0; j < 4; ++j) acc[i][j] = 0.f;

    for (int k0 = kbase; k0 < kbase + 256; k0 += 32) {
#pragma unroll
        for (int p = 0; p < 2; ++p) {
            const int r = lr + p * 32;
            const int b = r >> 4, s = r & 15;
            float4 va = *(const float4*)&x[(b*Tn + s)*Cn + k0 + lf4];
            As[lf4+0][r] = va.x; As[lf4+1][r] = va.y;
            As[lf4+2][r] = va.z; As[lf4+3][r] = va.w;
            const int jg = jt*64 + r;
            float4 vb = *(const float4*)&Wa[(Cn + jg)*Cn + k0 + lf4];
            Bs[lf4+0][r] = vb.x; Bs[lf4+1][r] = vb.y;
            Bs[lf4+2][r] = vb.z; Bs[lf4+3][r] = vb.w;
        }
        __syncthreads();
#pragma unroll 8
        for (int kk = 0; kk < 32; ++kk) {
            float4 a = *(const float4*)&As[kk][m0];
            float4 b = *(const float4*)&Bs[kk][n0];
            acc[0][0] += a.x*b.x; acc[0][1] += a.x*b.y; acc[0][2] += a.x*b.z; acc[0][3] += a.x*b.w;
            acc[1][0] += a.y*b.x; acc[1][1] += a.y*b.y; acc[1][2] += a.y*b.z; acc[1][3] += a.y*b.w;
            acc[2][0] += a.z*b.x; acc[2][1] += a.z*b.y; acc[2][2] += a.z*b.z; acc[2][3] += a.z*b.w;
            acc[3][0] += a.w*b.x; acc[3][1] += a.w*b.y; acc[3][2] += a.w*b.z; acc[3][3] += a.w*b.w;
        }
        __syncthreads();
    }
#pragma unroll
    for (int i = 0; i < 4; ++i) {
        const int r = m0 + i;
#pragma unroll
        for (int j = 0; j < 4; ++j)
            g_kvp[(ks*64 + r)*2048 + jt*64 + n0 + j] = acc[i][j];
    }
}

// ---------------------------------------------------------------------------
// K2: merged KQ / VP^T, reading kv partials directly (reduce folded in).
//   z=0: KQ[b,h,s,c] = 0.125*sum_d Wq[h*64+d,c]*k[b,s,h*64+d] -> bf16 planes
//   z=1: VP[b,h,s,j] = sum_d v[b,s,h*64+d]*Wp[j,h*64+d] -> VPT[b][j][hk] planes
// ---------------------------------------------------------------------------
__global__ __launch_bounds__(256) void kqvp_kernel(const float* __restrict__ Wa,
                                                   const float* __restrict__ Wp) {
    __shared__ float smem[12288];                    // 48KB
    float (*Ws)[128] = (float(*)[128])smem;          // [d][c or j]
    float (*ts)[64]  = (float(*)[64])(smem + 8192);  // [d][r]
    const int ct  = blockIdx.x;    // 0..7
    const int h   = blockIdx.y;    // 0..15
    const int z   = blockIdx.z;    // 0..1
    const int tid = threadIdx.x;
    const int vcol = (z == 0) ? h*HDn : 1024 + h*HDn;   // k or v region of kvp

    if (z == 0) {
#pragma unroll
        for (int p = 0; p < 8; ++p) {
            const int idx = tid + p*256;
            const int d   = idx >> 5;
            const int f4  = (idx & 31) << 2;
            float4 v = *(const float4*)&Wa[(h*HDn + d)*Cn + ct*128 + f4];
            *(float4*)&Ws[d][f4] = v;
        }
    } else {
#pragma unroll
        for (int p = 0; p < 8; ++p) {
            const int idx = tid + p*256;
            const int j   = idx >> 4;
            const int f4  = (idx & 15) << 2;
            float4 v = *(const float4*)&Wp[(ct*128 + j)*Cn + h*HDn + f4];
            Ws[f4+0][j] = v.x; Ws[f4+1][j] = v.y;
            Ws[f4+2][j] = v.z; Ws[f4+3][j] = v.w;
        }
    }
#pragma unroll
    for (int p = 0; p < 4; ++p) {
        const int idx = tid + p*256;
        const int r   = idx >> 4;
        const int f4  = (idx & 15) << 2;
        float4 s = make_float4(0.f, 0.f, 0.f, 0.f);
#pragma unroll
        for (int ksp = 0; ksp < 4; ++ksp) {
            float4 v = *(const float4*)&g_kvp[(ksp*64 + r)*2048 + vcol + f4];
            s.x += v.x; s.y += v.y; s.z += v.z; s.w += v.w;
        }
        ts[f4+0][r] = s.x; ts[f4+1][r] = s.y;
        ts[f4+2][r] = s.z; ts[f4+3][r] = s.w;
    }
    __syncthreads();

    const int r0 = (tid >> 4) << 2;
    const int c0 = (tid & 15) << 3;
    float acc[4][8];
#pragma unroll
    for (int i = 0; i < 4; ++i)
#pragma unroll
        for (int j = 0; j < 8; ++j) acc[i][j] = 0.f;

#pragma unroll 8
    for (int d = 0; d < 64; ++d) {
        float4 a  = *(const float4*)&ts[d][r0];
        float4 b0 = *(const float4*)&Ws[d][c0];
        float4 b1 = *(const float4*)&Ws[d][c0+4];
        const float av[4] = {a.x, a.y, a.z, a.w};
        const float bv[8] = {b0.x,b0.y,b0.z,b0.w,b1.x,b1.y,b1.z,b1.w};
#pragma unroll
        for (int i = 0; i < 4; ++i)
#pragma unroll
            for (int j = 0; j < 8; ++j) acc[i][j] += av[i]*bv[j];
    }

    if (z == 0) {
        // KQ bf16 planes, contiguous 16B stores
#pragma unroll
        for (int i = 0; i < 4; ++i) {
            const int r = r0 + i, b = r >> 4, s = r & 15;
            const int base = (b*HKn + h*KSn + s)*Cn + ct*128 + c0;
            bf16 hi[8], lo[8];
#pragma unroll
            for (int j = 0; j < 8; ++j) split2(acc[i][j] * 0.125f, hi[j], lo[j]);
            uint4 uh = make_uint4(pk2(hi[0],hi[1]), pk2(hi[2],hi[3]),
                                  pk2(hi[4],hi[5]), pk2(hi[6],hi[7]));
            uint4 ul = make_uint4(pk2(lo[0],lo[1]), pk2(lo[2],lo[3]),
                                  pk2(lo[4],lo[5]), pk2(lo[6],lo[7]));
            *(uint4*)&g_KQh[base] = uh;
            *(uint4*)&g_KQl[base] = ul;
        }
    } else {
        // transpose through smem -> VPT[b][j][hk] contiguous 32B runs
        __syncthreads();
        float* tp = smem;                       // [r 64][129]
#pragma unroll
        for (int i = 0; i < 4; ++i)
#pragma unroll
            for (int j = 0; j < 8; ++j)
                tp[(r0+i)*129 + c0 + j] = acc[i][j];
        __syncthreads();
#pragma unroll
        for (int p = 0; p < 2; ++p) {
            const int run = tid + p*256;        // 0..511
            const int bb  = run >> 7;           // batch
            const int j   = run & 127;
            bf16 hi[16], lo[16];
#pragma unroll
            for (int s = 0; s < 16; ++s)
                split2(tp[(bb*16 + s)*129 + j], hi[s], lo[s]);
            const int dst = (bb*Cn + ct*128 + j)*HKn + h*KSn;
            *(uint4*)&g_VPTh[dst]   = make_uint4(pk2(hi[0],hi[1]), pk2(hi[2],hi[3]),
                                                 pk2(hi[4],hi[5]), pk2(hi[6],hi[7]));
            *(uint4*)&g_VPTh[dst+8] = make_uint4(pk2(hi[8],hi[9]), pk2(hi[10],hi[11]),
                                                 pk2(hi[12],hi[13]), pk2(hi[14],hi[15]));
            *(uint4*)&g_VPTl[dst]   = make_uint4(pk2(lo[0],lo[1]), pk2(lo[2],lo[3]),
                                                 pk2(lo[4],lo[5]), pk2(lo[6],lo[7]));
            *(uint4*)&g_VPTl[dst+8] = make_uint4(pk2(lo[8],lo[9]), pk2(lo[10],lo[11]),
                                                 pk2(lo[12],lo[13]), pk2(lo[14],lo[15]));
        }
    }
}

// ---------------------------------------------------------------------------
// K3: attn partial logits via HMMA. CTA tile 128(t) x 64(hk), k-chunk 32,
// split-K x2. grid (4 n, 8 m, 8 b*ks), 256 thr (8 warps, 4x2 of 32x32).
// ---------------------------------------------------------------------------
__global__ __launch_bounds__(256,2) void attn_mma(const float* __restrict__ x) {
    __shared__ bf16 sm[384*LDT];                 // Ah|Al|Bh|Bl, 30KB
    bf16* Ah = sm;
    bf16* Bh = sm + 256*LDT;
    const int tid  = threadIdx.x;
    const int nIdx = blockIdx.x;                 // 0..3
    const int mIdx = blockIdx.y;                 // 0..7
    const int zb   = blockIdx.z;                 // 0..7
    const int b = zb >> 1, ks = zb & 1;
    const int trow0 = b*Tn + mIdx*128;
    const int n0 = nIdx*64;
    const int lane = tid & 31, wid = tid >> 5;
    const int mBase = (wid & 3) * 32, nBase = (wid >> 2) * 32;

    const int aR = (lane & 7) + ((lane >> 3) & 1)*8;
    const int aC = (lane >> 4)*8;
    const int bR = (lane & 7) + (lane >> 4)*8;
    const int bC = ((lane >> 3) & 1)*8;

    float acc[2][4][4];
#pragma unroll
    for (int mb = 0; mb < 2; ++mb)
#pragma unroll
        for (int nb = 0; nb < 4; ++nb)
#pragma unroll
            for (int q = 0; q < 4; ++q) acc[mb][nb][q] = 0.f;

    for (int k0 = ks*512; k0 < ks*512 + 512; k0 += 32) {
        // A: x fp32 -> hi/lo bf16 inline
#pragma unroll
        for (int p = 0; p < 4; ++p) {
            const int idx = tid + p*256;
            const int row = idx >> 3, kq = (idx & 7) * 4;
            float4 v = *(const float4*)&x[(trow0+row)*Cn + k0 + kq];
            bf16 hx,lx,hy,ly,hz,lz,hw,lw;
            split2(v.x,hx,lx); split2(v.y,hy,ly);
            split2(v.z,hz,lz); split2(v.w,hw,lw);
            *(uint2*)&Ah[row*LDT + kq]           = make_uint2(pk2(hx,hy), pk2(hz,hw));
            *(uint2*)&Ah[128*LDT + row*LDT + kq] = make_uint2(pk2(lx,ly), pk2(lz,lw));
        }
        // B: KQ planes
        {
            const int row = tid >> 2, kq = (tid & 3) * 8;
            const int gi = (b*HKn + n0 + row)*Cn + k0 + kq;
            *(uint4*)&Bh[row*LDT + kq]          = *(const uint4*)&g_KQh[gi];
            *(uint4*)&Bh[64*LDT + row*LDT + kq] = *(const uint4*)&g_KQl[gi];
        }
        __syncthreads();
#pragma unroll
        for (int kk = 0; kk < 32; kk += 16) {
            uint32_t ah[2][4], al[2][4], bh2[2][4], bl2[2][4];
#pragma unroll
            for (int mb = 0; mb < 2; ++mb) {
                uint32_t ad = sptr(&Ah[(mBase + mb*16 + aR)*LDT + kk + aC]);
                ldsm4(ah[mb], ad);
                ldsm4(al[mb], ad + 128*LDT*2);
            }
#pragma unroll
            for (int q = 0; q < 2; ++q) {
                uint32_t bd = sptr(&Bh[(nBase + q*16 + bR)*LDT + kk + bC]);
                ldsm4(bh2[q], bd);
                ldsm4(bl2[q], bd + 64*LDT*2);
            }
#pragma unroll
            for (int mb = 0; mb < 2; ++mb)
#pragma unroll
                for (int nb = 0; nb < 4; ++nb) {
                    const uint32_t* bhp = &bh2[nb>>1][(nb&1)*2];
                    const uint32_t* blp = &bl2[nb>>1][(nb&1)*2];
                    mma16816(acc[mb][nb], ah[mb], bhp);
                    mma16816(acc[mb][nb], ah[mb], blp);
                    mma16816(acc[mb][nb], al[mb], bhp);
                }
        }
        __syncthreads();
    }
    const int g = lane >> 2, c2 = (lane & 3) * 2;
#pragma unroll
    for (int mb = 0; mb < 2; ++mb)
#pragma unroll
        for (int nb = 0; nb < 4; ++nb) {
            const int row = trow0 + mBase + mb*16 + g;
            const int col = n0 + nBase + nb*8 + c2;
            *(float2*)&g_lp[(ks*(Bn*Tn) + row)*HKn + col] =
                make_float2(acc[mb][nb][0], acc[mb][nb][1]);
            *(float2*)&g_lp[(ks*(Bn*Tn) + row + 8)*HKn + col] =
                make_float2(acc[mb][nb][2], acc[mb][nb][3]);
        }
}

// ---------------------------------------------------------------------------
// K4: sum 2 split-K partials + masked softmax -> w bf16 planes.
// ---------------------------------------------------------------------------
__global__ __launch_bounds__(128) void softmax_kernel() {
    const int tid = threadIdx.x;
    const int t   = blockIdx.x * 8 + (tid >> 4);
    const int h   = tid & 15;
    const int base = t*HKn + h*KSn;

    float l[KSn];
#pragma unroll
    for (int q = 0; q < 4; ++q) {
        float4 v0 = *(const float4*)&g_lp[base + q*4];
        float4 v1 = *(const float4*)&g_lp[Bn*Tn*HKn + base + q*4];
        l[q*4+0] = v0.x + v1.x; l[q*4+1] = v0.y + v1.y;
        l[q*4+2] = v0.z + v1.z; l[q*4+3] = v0.w + v1.w;
    }
    const int tb  = t & (Tn - 1);
    const int cnt = (tb + 1 < KSn) ? tb + 1 : KSn;
    float m = -3.0e38f;
#pragma unroll
    for (int s = 0; s < KSn; ++s) if (s < cnt) m = fmaxf(m, l[s]);
    float e[KSn]; float sum = 0.f;
#pragma unroll
    for (int s = 0; s < KSn; ++s) {
        float v = (s < cnt) ? expf(l[s] - m) : 0.f;
        e[s] = v; sum += v;
    }
    const float inv = 1.f / sum;
    bf16 hi[16], lo[16];
#pragma unroll
    for (int s = 0; s < KSn; ++s) split2(e[s]*inv, hi[s], lo[s]);
    *(uint4*)&g_wh[base]   = make_uint4(pk2(hi[0],hi[1]), pk2(hi[2],hi[3]),
                                        pk2(hi[4],hi[5]), pk2(hi[6],hi[7]));
    *(uint4*)&g_wh[base+8] = make_uint4(pk2(hi[8],hi[9]), pk2(hi[10],hi[11]),
                                        pk2(hi[12],hi[13]), pk2(hi[14],hi[15]));
    *(uint4*)&g_wl[base]   = make_uint4(pk2(lo[0],lo[1]), pk2(lo[2],lo[3]),
                                        pk2(lo[4],lo[5]), pk2(lo[6],lo[7]));
    *(uint4*)&g_wl[base+8] = make_uint4(pk2(lo[8],lo[9]), pk2(lo[10],lo[11]),
                                        pk2(lo[12],lo[13]), pk2(lo[14],lo[15]));
}

// ---------------------------------------------------------------------------
// K5: out = w @ VP via HMMA. CTA tile 128(t) x 64(j), K=256 (8 chunks).
// grid (16 n, 8 m, 4 b), 256 thr.
// ---------------------------------------------------------------------------
__global__ __launch_bounds__(256,2) void out_mma(float* __restrict__ out) {
    __shared__ bf16 sm[384*LDT];
    bf16* Ah = sm;
    bf16* Bh = sm + 256*LDT;
    const int tid  = threadIdx.x;
    const int nIdx = blockIdx.x;                 // 0..15
    const int mIdx = blockIdx.y;                 // 0..7
    const int b    = blockIdx.z;
    const int trow0 = b*Tn + mIdx*128;
    const int j0 = nIdx*64;
    const int lane = tid & 31, wid = tid >> 5;
    const int mBase = (wid & 3) * 32, nBase = (wid >> 2) * 32;

    const int aR = (lane & 7) + ((lane >> 3) & 1)*8;
    const int aC = (lane >> 4)*8;
    const int bR = (lane & 7) + (lane >> 4)*8;
    const int bC = ((lane >> 3) & 1)*8;

    float acc[2][4][4];
#pragma unroll
    for (int mb = 0; mb < 2; ++mb)
#pragma unroll
        for (int nb = 0; nb < 4; ++nb)
#pragma unroll
            for (int q = 0; q < 4; ++q) acc[mb][nb][q] = 0.f;

    for (int k0 = 0; k0 < HKn; k0 += 32) {
#pragma unroll
        for (int p = 0; p < 2; ++p) {            // A: w planes
            const int idx = tid + p*256;
            const int row = idx >> 2, kq = (idx & 3) * 8;
            const int gi = (trow0+row)*HKn + k0 + kq;
            *(uint4*)&Ah[row*LDT + kq]           = *(const uint4*)&g_wh[gi];
            *(uint4*)&Ah[128*LDT + row*LDT + kq] = *(const uint4*)&g_wl[gi];
        }
        {                                        // B: VPT planes
            const int row = tid >> 2, kq = (tid & 3) * 8;
            const int gi = (b*Cn + j0 + row)*HKn + k0 + kq;
            *(uint4*)&Bh[row*LDT + kq]          = *(const uint4*)&g_VPTh[gi];
            *(uint4*)&Bh[64*LDT + row*LDT + kq] = *(const uint4*)&g_VPTl[gi];
        }
        __syncthreads();
#pragma unroll
        for (int kk = 0; kk < 32; kk += 16) {
            uint32_t ah[2][4], al[2][4], bh2[2][4], bl2[2][4];
#pragma unroll
            for (int mb = 0; mb < 2; ++mb) {
                uint32_t ad = sptr(&Ah[(mBase + mb*16 + aR)*LDT + kk + aC]);
                ldsm4(ah[mb], ad);
                ldsm4(al[mb], ad + 128*LDT*2);
            }
#pragma unroll
            for (int q = 0; q < 2; ++q) {
                uint32_t bd = sptr(&Bh[(nBase + q*16 + bR)*LDT + kk + bC]);
                ldsm4(bh2[q], bd);
                ldsm4(bl2[q], bd + 64*LDT*2);
            }
#pragma unroll
            for (int mb = 0; mb < 2; ++mb)
#pragma unroll
                for (int nb = 0; nb < 4; ++nb) {
                    const uint32_t* bhp = &bh2[nb>>1][(nb&1)*2];
                    const uint32_t* blp = &bl2[nb>>1][(nb&1)*2];
                    mma16816(acc[mb][nb], ah[mb], bhp);
                    mma16816(acc[mb][nb], ah[mb], blp);
                    mma16816(acc[mb][nb], al[mb], bhp);
                }
        }
        __syncthreads();
    }
    const int g = lane >> 2, c2 = (lane & 3) * 2;
#pragma unroll
    for (int mb = 0; mb < 2; ++mb)
#pragma unroll
        for (int nb = 0; nb < 4; ++nb) {
            const int row = trow0 + mBase + mb*16 + g;
            const int col = j0 + nBase + nb*8 + c2;
            *(float2*)&out[row*Cn + col] =
                make_float2(acc[mb][nb][0], acc[mb][nb][1]);
            *(float2*)&out[(row + 8)*Cn + col] =
                make_float2(acc[mb][nb][2], acc[mb][nb][3]);
        }
}

// ---------------------------------------------------------------------------
extern "C" void kernel_launch(void* const* d_in, const int* in_sizes, int n_in,
                              void* d_out, int out_size) {
    const float* x  = (const float*)d_in[0];
    const float* Wa = (const float*)d_in[1];
    const float* Wp = (const float*)d_in[2];
    float* out = (float*)d_out;

    kv3_kernel    <<<dim3(32, 4),    256>>>(x, Wa);
    kqvp_kernel   <<<dim3(8, 16, 2), 256>>>(Wa, Wp);
    attn_mma      <<<dim3(4, 8, 8),  256>>>(x);
    softmax_kernel<<<dim3(512),      128>>>();
    out_mma       <<<dim3(16, 8, 4), 256>>>(out);
}